// round 10
// baseline (speedup 1.0000x reference)
#include <cuda_runtime.h>

#define NBLK 148
#define NTHR 512
#define NWPC 16
#define NWARP (NBLK*NWPC)   // 2368
#define NL 6
#define DD 512
#define FF 2048
#define TD 1536
#define NBAR 35ULL

// ---------------- device scratch ----------------
__device__ __align__(16) float g_src35[35*DD];
__device__ __align__(16) float g_kv[NL*5*7*1024];
__device__ __align__(16) float g_q0[NL*5*DD];
__device__ __align__(16) float g_ctx5[NL*5*DD];
__device__ __align__(16) float g_vm[NL*5*DD];
__device__ __align__(16) float g_aggvraw[NL*DD];   // raw a1w@vm partials (sigmoid at consumer)
__device__ __align__(16) float g_qkv0[7*TD];
__device__ __align__(16) float g_msgN[6*DD];
__device__ __align__(16) float g_aggnraw[DD];
__device__ __align__(16) float g_hid[7*FF];   // [0..FF): t-path hid, [FF..7FF): rows1-6
__device__ __align__(16) float g_yraw[7*DD];  // row0: t-path RAW; rows1-6: s-path (bias+resid included)
__device__ unsigned long long g_bar;

// ---------------- helpers ----------------
__device__ __forceinline__ float wred(float v) {
#pragma unroll
    for (int o = 16; o; o >>= 1) v += __shfl_xor_sync(0xffffffffu, v, o);
    return v;
}
__device__ __forceinline__ float d4(float4 a, float4 b) {
    return fmaf(a.x, b.x, fmaf(a.y, b.y, fmaf(a.z, b.z, a.w * b.w)));
}
__device__ __forceinline__ void gridbar(unsigned long long base, int idx) {
    __syncthreads();
    if (threadIdx.x == 0) {
        asm volatile("red.release.gpu.add.u64 [%0], %1;" :: "l"(&g_bar), "l"(1ULL) : "memory");
        unsigned long long target = base + (unsigned long long)idx * NBLK;
        unsigned long long cur;
        for (;;) {
            asm volatile("ld.acquire.gpu.u64 %0, [%1];" : "=l"(cur) : "l"(&g_bar) : "memory");
            if (cur >= target) break;
            __nanosleep(64);
        }
    }
    __syncthreads();
}
__device__ __forceinline__ void cp4(float* dst, const float* src, int n) {
    float4* d4p = (float4*)dst;
    const float4* s4p = (const float4*)src;
    for (int i = threadIdx.x; i < (n >> 2); i += NTHR) d4p[i] = s4p[i];
}
// cp.async one 2KB chunk into a ring slot. Per-lane self-consistent: each lane
// copies exactly the bytes it will later read in ldw_s. One commit_group.
__device__ __forceinline__ void cpa_chunk(float* slot, const float* src) {
    unsigned s = (unsigned)__cvta_generic_to_shared(slot) + (threadIdx.x & 31)*16;
    const char* g = (const char*)src + (threadIdx.x & 31)*16;
#pragma unroll
    for (int i = 0; i < 4; i++)
        asm volatile("cp.async.cg.shared.global [%0], [%1], 16;"
                     :: "r"(s + i*512), "l"(g + i*512));
    asm volatile("cp.async.commit_group;" ::: "memory");
}
__device__ __forceinline__ void cpa_empty() {
    asm volatile("cp.async.commit_group;" ::: "memory");
}
__device__ __forceinline__ void cpa_wait1() {
    asm volatile("cp.async.wait_group 1;" ::: "memory");
}
__device__ __forceinline__ void ldw_s(const float* slot, float4* wv) {
    const float4* s4 = (const float4*)slot;
    int lane = threadIdx.x & 31;
#pragma unroll
    for (int i = 0; i < 4; i++) wv[i] = s4[lane + 32*i];
}
template<int K, int STR>
__device__ __forceinline__ void dotK(const float4* wv, const float* smbase, float* res) {
    int lane = threadIdx.x & 31;
    float acc[K];
#pragma unroll
    for (int k = 0; k < K; k++) {
        const float4* s4 = (const float4*)(smbase + k*STR);
        float a0 = d4(wv[0], s4[lane]);
        float a1 = d4(wv[1], s4[lane+32]);
        float a2 = d4(wv[2], s4[lane+64]);
        float a3 = d4(wv[3], s4[lane+96]);
        acc[k] = (a0 + a1) + (a2 + a3);
    }
#pragma unroll
    for (int o = 16; o; o >>= 1)
#pragma unroll
        for (int k = 0; k < K; k++)
            acc[k] += __shfl_xor_sync(0xffffffffu, acc[k], o);
#pragma unroll
    for (int k = 0; k < K; k++) res[k] = acc[k];
}
template<typename G>
__device__ __forceinline__ void ln_rowf(G get, const float* __restrict__ w,
                                        const float* __restrict__ b,
                                        float* __restrict__ out) {
    int lane = threadIdx.x & 31;
    float v[16]; float s = 0.f;
#pragma unroll
    for (int j = 0; j < 16; j++) { v[j] = get(j*32 + lane); s += v[j]; }
    s = wred(s);
    float mu = s * (1.f/512.f);
    float q = 0.f;
#pragma unroll
    for (int j = 0; j < 16; j++) { float d = v[j] - mu; q += d*d; }
    q = wred(q);
    float rs = rsqrtf(q * (1.f/512.f) + 1e-5f);
#pragma unroll
    for (int j = 0; j < 16; j++)
        out[j*32 + lane] = (v[j] - mu) * rs * w[j*32 + lane] + b[j*32 + lane];
}

__global__ void __launch_bounds__(NTHR)
fused_kernel(const float* __restrict__ feat, const float* __restrict__ role,
             const float* __restrict__ in_w, const float* __restrict__ in_b,
             const float* __restrict__ out_w, const float* __restrict__ out_b,
             const float* __restrict__ ln1w, const float* __restrict__ ln1b,
             const float* __restrict__ ln2w, const float* __restrict__ ln2b,
             const float* __restrict__ ln3w, const float* __restrict__ ln3b,
             const float* __restrict__ ln4w, const float* __restrict__ ln4b,
             const float* __restrict__ f1w1, const float* __restrict__ f1b1,
             const float* __restrict__ f1w2, const float* __restrict__ f1b2,
             const float* __restrict__ f2w1, const float* __restrict__ f2b1,
             const float* __restrict__ f2w2, const float* __restrict__ f2b2,
             const float* __restrict__ a1w, const float* __restrict__ a1b,
             const float* __restrict__ a2w, const float* __restrict__ a2b,
             float* __restrict__ out)
{
    extern __shared__ float sm[];
    float* ring = sm;                    // 16 warps * 2 slots * 512 = 16384
    float* psx  = sm + 16384;            // 7*512 persistent x rows
    float* psh1 = sm + 16384 + 3584;     // 6*512 LN1 output
    float* psh0 = sm + 16384 + 6656;     // 512   LN3 output
    float* sc   = sm + 16384 + 7168;     // scratch (<= 17920 floats)
    const int tid = threadIdx.x, lane = tid & 31, warp = tid >> 5;
    const int gw = blockIdx.x * NWPC + warp;
    const int gt = blockIdx.x * NTHR + tid;
    float* myring = ring + warp * 1024;  // slot0 at +0, slot1 at +512

    unsigned long long bbase = 0;
    if (tid == 0) {
        unsigned long long cur;
        asm volatile("ld.relaxed.gpu.u64 %0, [%1];" : "=l"(cur) : "l"(&g_bar));
        bbase = cur - (cur % (NBAR * (unsigned long long)NBLK));
    }
    int bi = 0;

    // chunk pointer maps
    auto p1ptr = [&](int t) -> const float* {
        return (t < 6144)
            ? in_w + ((size_t)(t >> 10)*TD + 512 + (t & 1023))*DD
            : in_w + ((size_t)((t - 6144) >> 9)*TD + ((t - 6144) & 511))*DD;
    };
    auto p3ptr = [&](int t) -> const float* {
        return a1w + (size_t)(t % 3072)*2560 + (t / 3072)*512;
    };

    // ---- Phase A: src for batches 1..5; pre-issue P1 chunks ----
    for (int i = gt; i < 35*DD; i += NBLK*NTHR) {
        int b5 = i / (7*DD); int rem = i % (7*DD); int s = rem / DD; int d = rem % DD;
        float v = feat[((b5+1)*7 + s)*DD + d];
        if (s > 0) v += role[((b5+1)*6 + (s-1))*DD + d];
        g_src35[i] = v;
    }
#pragma unroll
    for (int j = 0; j < 2; j++) {
        int t = gw + j*NWARP;
        if (t < 9216) cpa_chunk(myring + j*512, p1ptr(t)); else cpa_empty();
    }
    gridbar(bbase, ++bi);

    // ---- P1: K,V for (l,b>=1,s) and Q(token0) ----
    cp4(sc, g_src35, 35*DD);
    __syncthreads();
    {
        int k = 0;
        for (int t = gw; t < 9216; t += NWARP, k++) {
            cpa_wait1();
            float4 wv[4]; ldw_s(myring + (k&1)*512, wv);
            int nxt = t + 2*NWARP;
            if (nxt < 9216) cpa_chunk(myring + (k&1)*512, p1ptr(nxt)); else cpa_empty();
            if (t < 6144) {
                int l = t >> 10, e = t & 1023;
                float bias = in_b[l*TD + 512 + e];
                float res[7];
#pragma unroll
                for (int g = 0; g < 5; g++) {
                    dotK<7, DD>(wv, sc + g*7*DD, res);
                    if (lane == 0)
#pragma unroll
                        for (int j = 0; j < 7; j++)
                            g_kv[((size_t)(l*5 + g)*7 + j)*1024 + e] = res[j] + bias;
                }
            } else {
                int t2 = t - 6144;
                int l = t2 >> 9, e = t2 & 511;
                float bias = in_b[l*TD + e];
                float res[5];
                dotK<5, 7*DD>(wv, sc, res);
                if (lane == 0)
#pragma unroll
                    for (int j = 0; j < 5; j++)
                        g_q0[(l*5 + j)*DD + e] = res[j] + bias;
            }
        }
    }
    // pre-issue P2b (out_w rows) — consumed after P2a
#pragma unroll
    for (int j = 0; j < 2; j++) {
        int t = gw + j*NWARP;
        if (t < 3072) cpa_chunk(myring + j*512, out_w + (size_t)t*DD); else cpa_empty();
    }
    gridbar(bbase, ++bi);

    // ---- P2a: attention token0 for (l, b>=1): 30 CTA tasks; zero aggvraw ----
    if (blockIdx.x < 30) {
        int l = blockIdx.x / 5, b5 = blockIdx.x % 5;
        float* sq = sc; float* sk = sc + DD; float* satt = sc + DD + 7*DD;
        const float* kvb = g_kv + (size_t)(l*5 + b5)*7*1024;
        cp4(sq, g_q0 + (l*5 + b5)*DD, DD);
        for (int i = tid; i < 7*DD; i += NTHR) { int s = i >> 9, d = i & 511; sk[i] = kvb[s*1024 + d]; }
        __syncthreads();
        if (tid < 56) {
            int h = tid / 7, s = tid % 7;
            float a = 0.f;
            for (int d = 0; d < 64; d++) a += sq[h*64 + d] * sk[s*DD + h*64 + d];
            satt[tid] = a * 0.125f;
        }
        __syncthreads();
        if (tid < 8) {
            float m = -1e30f;
            for (int s = 0; s < 7; s++) m = fmaxf(m, satt[tid*7 + s]);
            float e[7], su = 0.f;
            for (int s = 0; s < 7; s++) { e[s] = expf(satt[tid*7 + s] - m); su += e[s]; }
            for (int s = 0; s < 7; s++) satt[tid*7 + s] = e[s] / su;
        }
        __syncthreads();
        for (int ch = tid; ch < DD; ch += NTHR) {
            int h = ch >> 6;
            float a = 0.f;
            for (int s = 0; s < 7; s++) a += satt[h*7 + s] * kvb[s*1024 + 512 + ch];
            g_ctx5[(l*5 + b5)*DD + ch] = a;
        }
    } else if (blockIdx.x == 30) {
        for (int i = tid; i < NL*DD; i += NTHR) g_aggvraw[i] = 0.f;
    }
    gridbar(bbase, ++bi);

    // ---- P2b: verb msgs ----
    cp4(sc, g_ctx5, 30*DD);
    __syncthreads();
    {
        int k = 0;
        for (int t = gw; t < 3072; t += NWARP, k++) {
            cpa_wait1();
            float4 wv[4]; ldw_s(myring + (k&1)*512, wv);
            int nxt = t + 2*NWARP;
            if (nxt < 3072) cpa_chunk(myring + (k&1)*512, out_w + (size_t)nxt*DD); else cpa_empty();
            int l = t >> 9, e = t & 511;
            float bias = out_b[t];
            float res[5];
            dotK<5, DD>(wv, sc + l*5*DD, res);
            if (lane == 0)
#pragma unroll
                for (int j = 0; j < 5; j++)
                    g_vm[(l*5 + j)*DD + e] = res[j] + bias;
        }
    }
#pragma unroll
    for (int j = 0; j < 2; j++) {
        int t = gw + j*NWARP;
        if (t < 15360) cpa_chunk(myring + j*512, p3ptr(t)); else cpa_empty();
    }
    gridbar(bbase, ++bi);

    // ---- P3: agg_verb raw partials (a1w chunks) ----
    cp4(sc, g_vm, 30*DD);
    __syncthreads();
    {
        int k = 0;
        for (int t = gw; t < 15360; t += NWARP, k++) {
            cpa_wait1();
            float4 wv[4]; ldw_s(myring + (k&1)*512, wv);
            int nxt = t + 2*NWARP;
            if (nxt < 15360) cpa_chunk(myring + (k&1)*512, p3ptr(nxt)); else cpa_empty();
            int r = t % 3072, s = t / 3072;
            int l = r >> 9;
            float res[1];
            dotK<1, DD>(wv, sc + l*2560 + s*512, res);
            if (lane == 0) atomicAdd(&g_aggvraw[r], res[0]);
        }
    }
    cp4(psx, feat, 7*DD);   // init persistent x = features[0]
#pragma unroll
    for (int j = 0; j < 2; j++) {
        int t = gw + j*NWARP;
        const float* rp = (t < 3584)
            ? ((t < 1536) ? in_w + (size_t)t*DD : f1w1 + (size_t)(t - 1536)*DD)
            : nullptr;
        if (rp) cpa_chunk(myring + j*512, rp); else cpa_empty();
    }
    gridbar(bbase, ++bi);

    // ================= layer loop =================
    for (int l = 0; l < NL; l++) {
        // ---- F1: ssrc/LN build + qkv + FFN1-up ----
        {
            float* ssrc = sc;   // 7*512
            if (warp == 0) {
                if (l == 0) {
                    for (int j = 0; j < 16; j++) ssrc[j*32 + lane] = psx[j*32 + lane];
                } else {
                    const float* fb = f2b2 + (l-1)*DD;
                    ln_rowf([&](int i){ return g_yraw[i] + fb[i] + psh0[i]; },
                            ln4w + (l-1)*DD, ln4b + (l-1)*DD, ssrc);
                    for (int j = 0; j < 16; j++) psx[j*32 + lane] = ssrc[j*32 + lane];
                }
            } else if (warp < 7) {
                const float* av = g_aggvraw + l*DD;
                const float* ab = a1b + l*DD;
                ln_rowf([&](int i){ return psx[warp*DD + i] + 1.f/(1.f + expf(-(av[i] + ab[i]))); },
                        ln1w + l*DD, ln1b + l*DD, psh1 + (warp-1)*DD);
            } else if (warp < 13) {
                int r = warp - 6;
                for (int j = 0; j < 16; j++) {
                    int d = j*32 + lane;
                    ssrc[r*DD + d] = psx[r*DD + d] + role[(r-1)*DD + d];
                }
            } else {
                int base = (warp - 13) * 1024;   // zero g_yraw rows 1-6
                for (int j = 0; j < 32; j++) g_yraw[DD + base + j*32 + lane] = 0.f;
            }
            __syncthreads();
            int k = 0;
            for (int t = gw; t < 3584; t += NWARP, k++) {
                cpa_wait1();
                float4 wv[4]; ldw_s(myring + (k&1)*512, wv);
                int nxt = t + 2*NWARP;
                if (nxt < 3584) {
                    const float* rp = (nxt < 1536) ? in_w + ((size_t)l*TD + nxt)*DD
                                                   : f1w1 + ((size_t)l*FF + (nxt - 1536))*DD;
                    cpa_chunk(myring + (k&1)*512, rp);
                } else cpa_empty();
                if (t < 1536) {
                    float res[7];
                    dotK<7, DD>(wv, ssrc, res);
                    if (lane == 0) {
                        float bias = in_b[l*TD + t];
#pragma unroll
                        for (int s = 0; s < 7; s++) g_qkv0[s*TD + t] = res[s] + bias;
                    }
                } else {
                    int e = t - 1536;
                    float res[6];
                    dotK<6, DD>(wv, psh1, res);
                    if (lane == 0) {
                        float bias = f1b1[l*FF + e];
#pragma unroll
                        for (int r = 0; r < 6; r++)
                            g_hid[(r+1)*FF + e] = fmaxf(res[r] + bias, 0.f);
                    }
                }
            }
            // pre-issue F2
            if (gw < 512) {
                cpa_chunk(myring, out_w + ((size_t)l*DD + gw)*DD);
                cpa_empty();
            } else {
                int u0 = gw - 512;
#pragma unroll
                for (int j = 0; j < 2; j++) {
                    int u = u0 + j*1856;
                    if (u < 2048)
                        cpa_chunk(myring + j*512, f1w2 + ((size_t)l*DD + (u & 511))*FF + (u >> 9)*512);
                    else cpa_empty();
                }
            }
        }
        gridbar(bbase, ++bi);

        // ---- F2: attention + msg (CTAs 0-31) | f1w2 chunks (CTAs 32+) ----
        {
            if (blockIdx.x < 32) {
                float* sqkv = sc;            // 10752
                float* sctx = sc + 10752;    // 3072
                float* satt = sc + 13824;    // 336
                cp4(sqkv, g_qkv0, 7*TD);
                __syncthreads();
                for (int t = tid; t < 336; t += NTHR) {
                    int qi = t / 56, r = t % 56, h = r / 7, s = r % 7;
                    const float* qv = sqkv + (qi+1)*TD + h*64;
                    const float* kv = sqkv + s*TD + 512 + h*64;
                    float a0=0,a1=0,a2=0,a3=0;
#pragma unroll
                    for (int d = 0; d < 64; d += 4) {
                        a0 = fmaf(qv[d],   kv[d],   a0);
                        a1 = fmaf(qv[d+1], kv[d+1], a1);
                        a2 = fmaf(qv[d+2], kv[d+2], a2);
                        a3 = fmaf(qv[d+3], kv[d+3], a3);
                    }
                    satt[t] = ((a0+a1)+(a2+a3)) * 0.125f;
                }
                __syncthreads();
                if (tid < 48) {
                    float m = -1e30f;
                    for (int s = 0; s < 7; s++) m = fmaxf(m, satt[tid*7 + s]);
                    float e[7], su = 0.f;
                    for (int s = 0; s < 7; s++) { e[s] = expf(satt[tid*7 + s] - m); su += e[s]; }
                    for (int s = 0; s < 7; s++) satt[tid*7 + s] = e[s] / su;
                }
                __syncthreads();
                for (int i = tid; i < 6*DD; i += NTHR) {
                    int qi = i >> 9, ch = i & 511, h = ch >> 6;
                    float a = 0.f;
                    for (int s = 0; s < 7; s++) a += satt[qi*56 + h*7 + s] * sqkv[s*TD + 1024 + ch];
                    sctx[i] = a;
                }
                __syncthreads();
                {   // msg dot: one task per warp, weights already in slot0
                    cpa_wait1();
                    float4 wv[4]; ldw_s(myring, wv);
                    float res[6];
                    dotK<6, DD>(wv, sctx, res);
                    if (lane == 0) {
                        float bias = out_b[l*DD + gw];
#pragma unroll
                        for (int r = 0; r < 6; r++) g_msgN[r*DD + gw] = res[r] + bias;
                    }
                }
            } else {
                float* shid = sc;   // 6*2048
                cp4(shid, g_hid + FF, 6*FF);
                if (blockIdx.x == 140)
                    for (int i = tid; i < DD; i += NTHR) g_aggnraw[i] = 0.f;
                __syncthreads();
                int u0 = gw - 512, k = 0;
                for (int u = u0; u < 2048; u += 1856, k++) {
                    cpa_wait1();
                    float4 wv[4]; ldw_s(myring + (k&1)*512, wv);
                    int nxt = u + 2*1856;
                    if (nxt < 2048)
                        cpa_chunk(myring + (k&1)*512, f1w2 + ((size_t)l*DD + (nxt & 511))*FF + (nxt >> 9)*512);
                    else cpa_empty();
                    int e = u & 511, s = u >> 9;
                    float res[6];
                    dotK<6, FF>(wv, shid + s*512, res);
                    if (lane == 0) {
                        float extra = (s == 0) ? f1b2[l*DD + e] : 0.f;
#pragma unroll
                        for (int r = 0; r < 6; r++) {
                            float add = res[r] + ((s == 0) ? (extra + psh1[r*DD + e]) : 0.f);
                            atomicAdd(&g_yraw[(r+1)*DD + e], add);
                        }
                    }
                }
            }
            // pre-issue F3 (a2w chunks)
#pragma unroll
            for (int j = 0; j < 2; j++) {
                int t = gw + j*NWARP;
                if (t < 3072)
                    cpa_chunk(myring + j*512, a2w + ((size_t)l*DD + (t & 511))*3072 + (t >> 9)*512);
                else cpa_empty();
            }
        }
        gridbar(bbase, ++bi);

        // ---- F3: agg_noun chunks ----
        {
            cp4(sc, g_msgN, 6*DD);
            if (blockIdx.x == 140)
                for (int i = tid; i < DD; i += NTHR) g_yraw[i] = 0.f;
            __syncthreads();
            int k = 0;
            for (int t = gw; t < 3072; t += NWARP, k++) {
                cpa_wait1();
                float4 wv[4]; ldw_s(myring + (k&1)*512, wv);
                int nxt = t + 2*NWARP;
                if (nxt < 3072)
                    cpa_chunk(myring + (k&1)*512, a2w + ((size_t)l*DD + (nxt & 511))*3072 + (nxt >> 9)*512);
                else cpa_empty();
                int e = t & 511, s = t >> 9;
                float res[1];
                dotK<1, DD>(wv, sc + s*512, res);
                if (lane == 0) atomicAdd(&g_aggnraw[e], res[0]);
            }
            // pre-issue F4 (f2w1 rows)
#pragma unroll
            for (int j = 0; j < 2; j++) {
                int t = gw + j*NWARP;
                if (t < 2048) cpa_chunk(myring + j*512, f2w1 + ((size_t)l*FF + t)*DD);
                else cpa_empty();
            }
        }
        gridbar(bbase, ++bi);

        // ---- F4: LN3 + LN2 + FFN2-up ----
        {
            if (warp == 0) {
                const float* ab = a2b + l*DD;
                ln_rowf([&](int i){
                            float a = g_aggnraw[i] + ab[i];
                            return psx[i] + 1.f / (1.f + expf(-a));
                        }, ln3w + l*DD, ln3b + l*DD, psh0);
            } else if (warp < 7) {
                ln_rowf([&](int i){ return g_yraw[warp*DD + i]; },
                        ln2w + l*DD, ln2b + l*DD, psx + warp*DD);
            }
            __syncthreads();
            int k = 0;
            for (int t = gw; t < 2048; t += NWARP, k++) {
                cpa_wait1();
                float4 wv[4]; ldw_s(myring + (k&1)*512, wv);
                int nxt = t + 2*NWARP;
                if (nxt < 2048) cpa_chunk(myring + (k&1)*512, f2w1 + ((size_t)l*FF + nxt)*DD);
                else cpa_empty();
                float res[1];
                dotK<1, DD>(wv, psh0, res);
                if (lane == 0) g_hid[t] = fmaxf(res[0] + f2b1[l*FF + t], 0.f);
            }
            // pre-issue F5 (f2w2 chunks)
#pragma unroll
            for (int j = 0; j < 2; j++) {
                int t = gw + j*NWARP;
                if (t < 2048)
                    cpa_chunk(myring + j*512, f2w2 + ((size_t)l*DD + (t & 511))*FF + (t >> 9)*512);
                else cpa_empty();
            }
        }
        gridbar(bbase, ++bi);

        // ---- F5: FFN2-down chunks (RAW partials; bias+resid at LN4 reader) ----
        {
            cp4(sc, g_hid, FF);
            __syncthreads();
            int k = 0;
            for (int t = gw; t < 2048; t += NWARP, k++) {
                cpa_wait1();
                float4 wv[4]; ldw_s(myring + (k&1)*512, wv);
                int nxt = t + 2*NWARP;
                if (nxt < 2048)
                    cpa_chunk(myring + (k&1)*512, f2w2 + ((size_t)l*DD + (nxt & 511))*FF + (nxt >> 9)*512);
                else cpa_empty();
                int e = t & 511, s = t >> 9;
                float res[1];
                dotK<1, DD>(wv, sc + s*512, res);
                if (lane == 0) atomicAdd(&g_yraw[e], res[0]);
            }
            // pre-issue next layer's F1
            if (l + 1 < NL) {
#pragma unroll
                for (int j = 0; j < 2; j++) {
                    int t = gw + j*NWARP;
                    if (t < 3584) {
                        const float* rp = (t < 1536) ? in_w + ((size_t)(l+1)*TD + t)*DD
                                                     : f1w1 + ((size_t)(l+1)*FF + (t - 1536))*DD;
                        cpa_chunk(myring + j*512, rp);
                    } else cpa_empty();
                }
            }
        }
        gridbar(bbase, ++bi);
    }

    // ---- final output: LN4 row0, LN2 rows1-6 ----
    if (blockIdx.x == 0 && warp < 7) {
        if (warp == 0) {
            const float* fb = f2b2 + 5*DD;
            ln_rowf([&](int i){ return g_yraw[i] + fb[i] + psh0[i]; },
                    ln4w + 5*DD, ln4b + 5*DD, out);
        } else {
            ln_rowf([&](int i){ return g_yraw[warp*DD + i]; },
                    ln2w + 5*DD, ln2b + 5*DD, out + warp*DD);
        }
    }
}

#define SMEM_BYTES ((16384 + 7168 + 17920) * 4)

extern "C" void kernel_launch(void* const* d_in, const int* in_sizes, int n_in,
                              void* d_out, int out_size) {
    cudaFuncSetAttribute(fused_kernel, cudaFuncAttributeMaxDynamicSharedMemorySize, SMEM_BYTES);
    fused_kernel<<<NBLK, NTHR, SMEM_BYTES>>>(
        (const float*)d_in[0],  (const float*)d_in[1],
        (const float*)d_in[2],  (const float*)d_in[3],
        (const float*)d_in[4],  (const float*)d_in[5],
        (const float*)d_in[6],  (const float*)d_in[7],
        (const float*)d_in[8],  (const float*)d_in[9],
        (const float*)d_in[10], (const float*)d_in[11],
        (const float*)d_in[12], (const float*)d_in[13],
        (const float*)d_in[14], (const float*)d_in[15],
        (const float*)d_in[16], (const float*)d_in[17],
        (const float*)d_in[18], (const float*)d_in[19],
        (const float*)d_in[20], (const float*)d_in[21],
        (const float*)d_in[22], (const float*)d_in[23],
        (const float*)d_in[24], (const float*)d_in[25],
        (float*)d_out);
}